// round 7
// baseline (speedup 1.0000x reference)
#include <cuda_runtime.h>
#include <math.h>

#define H 8192
#define NSPLIT 64
#define ROWS_PER_SPLIT (H / NSPLIT)   // 128
#define COLBLKS (H / (256 * 4))       // 8
#define UNROLL 8

// Scratch (no cudaMalloc allowed)
__device__ float g_part[NSPLIT * H];      // layer-2 partials (2 MB, L2)
__device__ float g_pen_part[COLBLKS * 8]; // head partials (one per column group)
__device__ int   g_col_cnt[COLBLKS];      // completion counters per column group
__device__ int   g_pen_cnt;               // completion counter for head

// ---- Single fused kernel: h1 recompute + sparse compaction + split-K GEMV +
//      last-arriver reduce + head + masked softmax. One launch total. ----
__global__ void __launch_bounds__(256, 4) k_all(const float* __restrict__ state,
                                                const float* __restrict__ W1,
                                                const float* __restrict__ b1,
                                                const float* __restrict__ W2,
                                                const float* __restrict__ b2,
                                                const float* __restrict__ W3,
                                                const float* __restrict__ b3,
                                                float* __restrict__ out) {
    __shared__ float s[42];
    __shared__ float xs[ROWS_PER_SPLIT];
    __shared__ int   ridx[ROWS_PER_SPLIT];
    __shared__ int   wcnt[4];
    __shared__ int   flag;
    int t = threadIdx.x;
    int lane = t & 31, wid = t >> 5;
    if (t < 42) s[t] = state[t];
    __syncthreads();

    // ---- Phase 1: compute h1 slice + order-preserving compaction ----
    int r0 = blockIdx.y * ROWS_PER_SPLIT;
    float v = 0.0f;
    int pos = 0;
    if (t < ROWS_PER_SPLIT) {
        float acc = b1[r0 + t];
        #pragma unroll
        for (int k = 0; k < 42; k++)
            acc = fmaf(s[k], __ldg(W1 + (size_t)k * H + r0 + t), acc);
        v = fmaxf(acc, 0.0f);
        unsigned m = __ballot_sync(0xFFFFFFFF, v > 0.0f);
        pos = __popc(m & ((1u << lane) - 1));
        if (lane == 0) wcnt[wid] = __popc(m);
    }
    __syncthreads();
    int nr = wcnt[0] + wcnt[1] + wcnt[2] + wcnt[3];
    if (t < ROWS_PER_SPLIT && v > 0.0f) {
        int off = pos;
        for (int w = 0; w < 4; w++) if (w < wid) off += wcnt[w];
        xs[off]   = v;
        ridx[off] = r0 + t;
    }
    __syncthreads();

    // ---- Phase 2: sparse split-K GEMV partial ----
    int c = (blockIdx.x * 256 + t) * 4;
    float4 acc = make_float4(0.f, 0.f, 0.f, 0.f);

    int nr8 = nr & ~(UNROLL - 1);
    for (int rb = 0; rb < nr8; rb += UNROLL) {
        float4 w[UNROLL];
        #pragma unroll
        for (int u = 0; u < UNROLL; u++)
            w[u] = __ldcs(reinterpret_cast<const float4*>(
                       W2 + (size_t)ridx[rb + u] * H + c));
        #pragma unroll
        for (int u = 0; u < UNROLL; u++) {
            float xv = xs[rb + u];
            acc.x = fmaf(xv, w[u].x, acc.x);
            acc.y = fmaf(xv, w[u].y, acc.y);
            acc.z = fmaf(xv, w[u].z, acc.z);
            acc.w = fmaf(xv, w[u].w, acc.w);
        }
    }
    for (int r = nr8; r < nr; r++) {
        float4 w = __ldcs(reinterpret_cast<const float4*>(
                       W2 + (size_t)ridx[r] * H + c));
        float xv = xs[r];
        acc.x = fmaf(xv, w.x, acc.x);
        acc.y = fmaf(xv, w.y, acc.y);
        acc.z = fmaf(xv, w.z, acc.z);
        acc.w = fmaf(xv, w.w, acc.w);
    }
    *reinterpret_cast<float4*>(g_part + (size_t)blockIdx.y * H + c) = acc;

    // ---- Phase 3: last-arriver per column group reduces its 64 partials ----
    __syncthreads();
    __threadfence();
    if (t == 0) {
        int old = atomicAdd(&g_col_cnt[blockIdx.x], 1);
        flag = (old == NSPLIT - 1);
        if (flag) g_col_cnt[blockIdx.x] = 0;   // reset for next replay
    }
    __syncthreads();
    if (!flag) return;
    __threadfence();   // acquire: all 64 partial writes now visible

    // reduce 64 partials for this block's 4 columns, fixed index order
    float4 racc = *reinterpret_cast<const float4*>(b2 + c);
    #pragma unroll
    for (int sb = 0; sb < NSPLIT; sb += UNROLL) {
        float4 p[UNROLL];
        #pragma unroll
        for (int u = 0; u < UNROLL; u++)
            p[u] = *reinterpret_cast<const float4*>(g_part + (size_t)(sb + u) * H + c);
        #pragma unroll
        for (int u = 0; u < UNROLL; u++) {
            racc.x += p[u].x; racc.y += p[u].y;
            racc.z += p[u].z; racc.w += p[u].w;
        }
    }
    float h2[4] = { fmaxf(racc.x, 0.f), fmaxf(racc.y, 0.f),
                    fmaxf(racc.z, 0.f), fmaxf(racc.w, 0.f) };

    // head: pen contribution of this thread's 4 columns
    float pen[8];
    #pragma unroll
    for (int n = 0; n < 8; n++) pen[n] = 0.0f;
    #pragma unroll
    for (int jj = 0; jj < 4; jj++) {
        int j = c + jj;
        float4 w0 = *reinterpret_cast<const float4*>(W3 + (size_t)j * 8);
        float4 w1 = *reinterpret_cast<const float4*>(W3 + (size_t)j * 8 + 4);
        float hv = h2[jj];
        pen[0] = fmaf(hv, w0.x, pen[0]);  pen[1] = fmaf(hv, w0.y, pen[1]);
        pen[2] = fmaf(hv, w0.z, pen[2]);  pen[3] = fmaf(hv, w0.w, pen[3]);
        pen[4] = fmaf(hv, w1.x, pen[4]);  pen[5] = fmaf(hv, w1.y, pen[5]);
        pen[6] = fmaf(hv, w1.z, pen[6]);  pen[7] = fmaf(hv, w1.w, pen[7]);
    }

    __shared__ float red[256][8];
    #pragma unroll
    for (int n = 0; n < 8; n++) red[t][n] = pen[n];
    __syncthreads();
    for (int stride = 128; stride > 0; stride >>= 1) {
        if (t < stride) {
            #pragma unroll
            for (int n = 0; n < 8; n++) red[t][n] += red[t + stride][n];
        }
        __syncthreads();
    }
    if (t < 8) g_pen_part[blockIdx.x * 8 + t] = red[0][t];

    // ---- Phase 4: very last block does bias + value + masked softmax ----
    __syncthreads();
    __threadfence();
    if (t == 0) {
        int old = atomicAdd(&g_pen_cnt, 1);
        flag = (old == COLBLKS - 1);
        if (flag) g_pen_cnt = 0;   // reset for next replay
    }
    __syncthreads();
    if (!flag) return;
    __threadfence();

    if (t == 0) {
        float pens[8];
        #pragma unroll
        for (int n = 0; n < 8; n++) {
            float a = b3[n];
            #pragma unroll
            for (int b = 0; b < COLBLKS; b++)
                a += g_pen_part[b * 8 + n];
            pens[n] = a;
        }
        float value = pens[7];
        bool legal[7];
        float mx = -INFINITY;
        #pragma unroll
        for (int n = 0; n < 7; n++) {
            legal[n] = (state[n] == 0.0f);
            if (legal[n] && pens[n] > mx) mx = pens[n];
        }
        float e[7];
        float sum = 0.0f;
        #pragma unroll
        for (int n = 0; n < 7; n++) {
            e[n] = legal[n] ? expf(pens[n] - mx) : 0.0f;
            sum += e[n];
        }
        float inv = 1.0f / sum;
        out[0] = value;
        #pragma unroll
        for (int n = 0; n < 7; n++) out[1 + n] = e[n] * inv;
    }
}

extern "C" void kernel_launch(void* const* d_in, const int* in_sizes, int n_in,
                              void* d_out, int out_size) {
    const float* state = (const float*)d_in[0];
    const float* W1    = (const float*)d_in[1];
    const float* b1    = (const float*)d_in[2];
    const float* W2    = (const float*)d_in[3];
    const float* b2    = (const float*)d_in[4];
    const float* W3    = (const float*)d_in[5];
    const float* b3    = (const float*)d_in[6];
    float* out = (float*)d_out;

    dim3 g(COLBLKS, NSPLIT);   // (8, 64) = 512 blocks — ONE launch
    k_all<<<g, 256>>>(state, W1, b1, W2, b2, W3, b3, out);
}

// round 8
// speedup vs baseline: 1.0009x; 1.0009x over previous
#include <cuda_runtime.h>
#include <math.h>

#define H 8192
#define NSPLIT 64
#define ROWS_PER_SPLIT (H / NSPLIT)   // 128
#define COLBLKS (H / (256 * 4))       // 8
#define UNROLL 8
#define SGRP 8                         // splits per k3a group

// Scratch (no cudaMalloc allowed)
__device__ float g_part[NSPLIT * H];          // layer-2 partials (2 MB, L2)
__device__ float g_part2[(NSPLIT / SGRP) * H];// stage-2 partials (256 KB)
__device__ float g_pen_part[32 * 8];          // head partials
__device__ int   g_done_cnt;                  // k3b completion counter

// ---- k2: fused h1-recompute + in-block sparse compaction + split-K GEMV ----
__global__ void __launch_bounds__(256, 4) k2_fused(const float* __restrict__ state,
                                                   const float* __restrict__ W1,
                                                   const float* __restrict__ b1,
                                                   const float* __restrict__ W2) {
    __shared__ float s[42];
    __shared__ float xs[ROWS_PER_SPLIT];
    __shared__ int   ridx[ROWS_PER_SPLIT];
    __shared__ int   wcnt[4];
    int t = threadIdx.x;
    int lane = t & 31, wid = t >> 5;
    if (t < 42) s[t] = state[t];
    __syncthreads();

    int r0 = blockIdx.y * ROWS_PER_SPLIT;

    float v = 0.0f;
    int pos = 0;
    if (t < ROWS_PER_SPLIT) {
        float acc = b1[r0 + t];
        #pragma unroll
        for (int k = 0; k < 42; k++)
            acc = fmaf(s[k], __ldg(W1 + (size_t)k * H + r0 + t), acc);
        v = fmaxf(acc, 0.0f);
        unsigned m = __ballot_sync(0xFFFFFFFF, v > 0.0f);
        pos = __popc(m & ((1u << lane) - 1));
        if (lane == 0) wcnt[wid] = __popc(m);
    }
    __syncthreads();
    int nr = wcnt[0] + wcnt[1] + wcnt[2] + wcnt[3];
    if (t < ROWS_PER_SPLIT && v > 0.0f) {
        int off = pos;
        for (int w = 0; w < 4; w++) if (w < wid) off += wcnt[w];
        xs[off]   = v;
        ridx[off] = r0 + t;
    }
    __syncthreads();

    int c = (blockIdx.x * 256 + t) * 4;
    float4 acc = make_float4(0.f, 0.f, 0.f, 0.f);

    int nr8 = nr & ~(UNROLL - 1);
    for (int rb = 0; rb < nr8; rb += UNROLL) {
        float4 w[UNROLL];
        #pragma unroll
        for (int u = 0; u < UNROLL; u++)
            w[u] = __ldcs(reinterpret_cast<const float4*>(
                       W2 + (size_t)ridx[rb + u] * H + c));
        #pragma unroll
        for (int u = 0; u < UNROLL; u++) {
            float xv = xs[rb + u];
            acc.x = fmaf(xv, w[u].x, acc.x);
            acc.y = fmaf(xv, w[u].y, acc.y);
            acc.z = fmaf(xv, w[u].z, acc.z);
            acc.w = fmaf(xv, w[u].w, acc.w);
        }
    }
    for (int r = nr8; r < nr; r++) {
        float4 w = __ldcs(reinterpret_cast<const float4*>(
                       W2 + (size_t)ridx[r] * H + c));
        float xv = xs[r];
        acc.x = fmaf(xv, w.x, acc.x);
        acc.y = fmaf(xv, w.y, acc.y);
        acc.z = fmaf(xv, w.z, acc.z);
        acc.w = fmaf(xv, w.w, acc.w);
    }
    *reinterpret_cast<float4*>(g_part + (size_t)blockIdx.y * H + c) = acc;
}

// ---- k3a: stage-1 reduce — 256 blocks, each sums SGRP=8 partials for 256 cols ----
__global__ void __launch_bounds__(256) k3a(void) {
    int t = threadIdx.x;
    int j = blockIdx.x * 256 + t;
    int g = blockIdx.y;
    float a[SGRP];
    #pragma unroll
    for (int sIdx = 0; sIdx < SGRP; sIdx++)
        a[sIdx] = g_part[(size_t)(g * SGRP + sIdx) * H + j];
    float acc = 0.0f;
    #pragma unroll
    for (int sIdx = 0; sIdx < SGRP; sIdx++) acc += a[sIdx];
    g_part2[(size_t)g * H + j] = acc;
}

// ---- k3b: stage-2 reduce + relu + W3 head + LAST-ARRIVER softmax (fused final) ----
__global__ void __launch_bounds__(256) k3b(const float* __restrict__ state,
                                           const float* __restrict__ b2,
                                           const float* __restrict__ W3,
                                           const float* __restrict__ b3,
                                           float* __restrict__ out) {
    __shared__ float red[256][8];
    __shared__ int   flag;
    int t = threadIdx.x;
    int j = blockIdx.x * 256 + t;

    float acc = b2[j];
    #pragma unroll
    for (int g = 0; g < NSPLIT / SGRP; g++)
        acc += g_part2[(size_t)g * H + j];
    float h2 = fmaxf(acc, 0.0f);

    float4 w0 = *reinterpret_cast<const float4*>(W3 + (size_t)j * 8);
    float4 w1 = *reinterpret_cast<const float4*>(W3 + (size_t)j * 8 + 4);
    red[t][0] = h2 * w0.x;  red[t][1] = h2 * w0.y;
    red[t][2] = h2 * w0.z;  red[t][3] = h2 * w0.w;
    red[t][4] = h2 * w1.x;  red[t][5] = h2 * w1.y;
    red[t][6] = h2 * w1.z;  red[t][7] = h2 * w1.w;
    __syncthreads();

    for (int stride = 128; stride > 0; stride >>= 1) {
        if (t < stride) {
            #pragma unroll
            for (int n = 0; n < 8; n++) red[t][n] += red[t + stride][n];
        }
        __syncthreads();
    }
    if (t < 8) g_pen_part[blockIdx.x * 8 + t] = red[0][t];

    // last-arriver among the 32 blocks does bias + value + masked softmax
    __syncthreads();
    __threadfence();
    if (t == 0) {
        int old = atomicAdd(&g_done_cnt, 1);
        flag = (old == 31);
        if (flag) g_done_cnt = 0;   // reset for graph replay
    }
    __syncthreads();
    if (!flag) return;
    __threadfence();   // all 32 g_pen_part writes visible

    if (t == 0) {
        float pens[8];
        #pragma unroll
        for (int n = 0; n < 8; n++) {
            float a = b3[n];
            #pragma unroll
            for (int b = 0; b < 32; b++)
                a += g_pen_part[b * 8 + n];
            pens[n] = a;
        }
        float value = pens[7];
        bool legal[7];
        float mx = -INFINITY;
        #pragma unroll
        for (int n = 0; n < 7; n++) {
            legal[n] = (state[n] == 0.0f);
            if (legal[n] && pens[n] > mx) mx = pens[n];
        }
        float e[7];
        float sum = 0.0f;
        #pragma unroll
        for (int n = 0; n < 7; n++) {
            e[n] = legal[n] ? expf(pens[n] - mx) : 0.0f;
            sum += e[n];
        }
        float inv = 1.0f / sum;
        out[0] = value;
        #pragma unroll
        for (int n = 0; n < 7; n++) out[1 + n] = e[n] * inv;
    }
}

extern "C" void kernel_launch(void* const* d_in, const int* in_sizes, int n_in,
                              void* d_out, int out_size) {
    const float* state = (const float*)d_in[0];
    const float* W1    = (const float*)d_in[1];
    const float* b1    = (const float*)d_in[2];
    const float* W2    = (const float*)d_in[3];
    const float* b2    = (const float*)d_in[4];
    const float* W3    = (const float*)d_in[5];
    const float* b3    = (const float*)d_in[6];
    float* out = (float*)d_out;

    dim3 g2(COLBLKS, NSPLIT);             // (8, 64) = 512 blocks
    k2_fused<<<g2, 256>>>(state, W1, b1, W2);

    dim3 g3(32, NSPLIT / SGRP);           // (32, 8) = 256 blocks
    k3a<<<g3, 256>>>();

    k3b<<<32, 256>>>(state, b2, W3, b3, out);
}